// round 5
// baseline (speedup 1.0000x reference)
#include <cuda_runtime.h>
#include <math.h>

#define T_SEQ 2048
#define BATCH 256
// Kernel B per k-quarter (32 k): RKQ in registers, SKQ in smem
#define RKQ 20
#define SKQ 12

typedef unsigned long long u64;

// xg scratch: [B][T][4H] fp32 = 1 GiB. __device__ global (no cudaMalloc allowed).
__device__ float g_xg[268435456];

// ---- f32x2 packed-math helpers (sm_103a FFMA2) --------------------------
__device__ __forceinline__ u64 pack2(float lo, float hi) {
    u64 r; asm("mov.b64 %0, {%1, %2};" : "=l"(r) : "f"(lo), "f"(hi)); return r;
}
__device__ __forceinline__ u64 dup2(float v) {
    u64 r; asm("mov.b64 %0, {%1, %1};" : "=l"(r) : "f"(v)); return r;
}
__device__ __forceinline__ void ffma2(u64& d, u64 a, u64 b) {
    asm("fma.rn.f32x2 %0, %1, %2, %0;" : "+l"(d) : "l"(a), "l"(b));
}
__device__ __forceinline__ u64 add2(u64 a, u64 b) {
    u64 r; asm("add.rn.f32x2 %0, %1, %2;" : "=l"(r) : "l"(a), "l"(b)); return r;
}
__device__ __forceinline__ void unpack2(u64 v, float& lo, float& hi) {
    asm("mov.b64 {%0, %1}, %2;" : "=f"(lo), "=f"(hi) : "l"(v));
}

__device__ __forceinline__ float sigf(float x) {
    return __fdividef(1.f, 1.f + __expf(-x));
}
// overflow-safe tanh: exp argument always <= 0
__device__ __forceinline__ float tanhx(float x) {
    float a = fabsf(x);
    float e = __expf(-2.f * a);
    float r = __fdividef(1.f - e, 1.f + e);
    return copysignf(r, x);
}

// ---------------------------------------------------------------------------
// Kernel A: xg = x @ Wih^T + bih + bhh  (unchanged; ~95% of fp32x2 roofline)
// ---------------------------------------------------------------------------
__global__ void __launch_bounds__(256, 2)
xg_gemm(const float* __restrict__ x, const float* __restrict__ Wih,
        const float* __restrict__ bih, const float* __restrict__ bhh)
{
    extern __shared__ float sm[];
    float* As = sm;
    float* B0 = sm + 8192;
    float* B1 = B0 + 8192;

    const int tid = threadIdx.x;
    const int tx = tid & 31;
    const int ty = tid >> 5;
    const long row0 = (long)blockIdx.x * 64;
    const int g0 = blockIdx.y * 128;

    {
        const float4* x4 = (const float4*)x + row0 * 32;
        float4* As4 = (float4*)As;
#pragma unroll
        for (int i = 0; i < 8; ++i) As4[i * 256 + tid] = x4[i * 256 + tid];
    }
    {
        const float4* w4 = (const float4*)Wih + (long)g0 * 32;
#pragma unroll
        for (int i = 0; i < 16; ++i) {
            int idx = i * 256 + tid;
            int q  = idx >> 7;
            int gl = idx & 127;
            float4 w = w4[(long)gl * 32 + q];
            float* dst = (gl < 64 ? B0 : B1) + (gl & 63);
            int k = q * 4;
            dst[(k + 0) * 64] = w.x;
            dst[(k + 1) * 64] = w.y;
            dst[(k + 2) * 64] = w.z;
            dst[(k + 3) * 64] = w.w;
        }
    }
    __syncthreads();

    u64 acc0[8], acc1[8];
#pragma unroll
    for (int i = 0; i < 8; ++i) { acc0[i] = 0ull; acc1[i] = 0ull; }

    const float4* As4 = (const float4*)As;

#pragma unroll 2
    for (int k4 = 0; k4 < 32; ++k4) {
        float4 a[8];
#pragma unroll
        for (int i = 0; i < 8; ++i) a[i] = As4[(ty * 8 + i) * 32 + k4];
#pragma unroll
        for (int c = 0; c < 4; ++c) {
            int k = 4 * k4 + c;
            u64 b0 = *(const u64*)(B0 + k * 64 + 2 * tx);
            u64 b1 = *(const u64*)(B1 + k * 64 + 2 * tx);
#pragma unroll
            for (int i = 0; i < 8; ++i) {
                float av = (c == 0) ? a[i].x : (c == 1) ? a[i].y
                          : (c == 2) ? a[i].z : a[i].w;
                u64 ad = dup2(av);
                ffma2(acc0[i], ad, b0);
                ffma2(acc1[i], ad, b1);
            }
        }
    }

    int c00 = g0 + 2 * tx, c10 = g0 + 64 + 2 * tx;
    float2 bv0 = make_float2(bih[c00] + bhh[c00], bih[c00 + 1] + bhh[c00 + 1]);
    float2 bv1 = make_float2(bih[c10] + bhh[c10], bih[c10 + 1] + bhh[c10 + 1]);

#pragma unroll
    for (int i = 0; i < 8; ++i) {
        long r = row0 + ty * 8 + i;
        float lo, hi;
        unpack2(acc0[i], lo, hi);
        *(float2*)&g_xg[r * 512 + c00] = make_float2(lo + bv0.x, hi + bv0.y);
        unpack2(acc1[i], lo, hi);
        *(float2*)&g_xg[r * 512 + c10] = make_float2(lo + bv1.x, hi + bv1.y);
    }
}

// ---------------------------------------------------------------------------
// Kernel B: LSTM recurrence. 128 CTAs x 2 rows, 512 threads/CTA.
// Warp layout: lane = 8*kq + (j&7), warp = j>>3. All 4 k-quarters of a hidden
// unit j live in ONE warp -> cross-k reduction via 2 rounds of SHFL.BFLY
// (each lane reduces only its assigned row = kq&1). ONE barrier per step.
// Weights: RKQ=20 k in registers, SKQ=12 k in smem per quarter.
// ---------------------------------------------------------------------------
__global__ void __launch_bounds__(512, 1)
lstm_rec(const float* __restrict__ Whh, const float* __restrict__ Wo,
         const float* __restrict__ bo, float* __restrict__ out)
{
    extern __shared__ float sm[];
    float* WIF = sm;                         // [4*SKQ][256] pairs (wi,wf)
    float* WGO = WIF + 4 * SKQ * 256;        // [4*SKQ][256] pairs (wg,wo)
    float* hbuf = WGO + 4 * SKQ * 256;       // [2][256] ping-pong (row*128+j)

    const int th = threadIdx.x;
    const int lane = th & 31, w = th >> 5;
    const int j  = (w << 3) | (lane & 7);    // hidden index 0..127
    const int kq = lane >> 3;                // k-quarter 0..3
    const int row = kq & 1;                  // row this lane finalizes/reduces
    const int b0 = blockIdx.x * 2;
    const int k0 = 32 * kq;

    // ---- smem weights: for each q, k in [32q+RKQ, 32q+32) -> ks = q*SKQ+kk
    for (int e = th; e < 4 * SKQ * 128; e += 512) {
        int jj = e & 127, ks = e >> 7;
        int q = ks / SKQ, kk = ks % SKQ;
        int k = 32 * q + RKQ + kk;
        float wi = Whh[(0 * 128 + jj) * 128 + k];
        float wf = Whh[(1 * 128 + jj) * 128 + k];
        float wg = Whh[(2 * 128 + jj) * 128 + k];
        float wo = Whh[(3 * 128 + jj) * 128 + k];
        *(float2*)&WIF[ks * 256 + 2 * jj] = make_float2(wi, wf);
        *(float2*)&WGO[ks * 256 + 2 * jj] = make_float2(wg, wo);
    }
    // ---- register weights: k in [32kq, 32kq+RKQ)
    u64 wifr[RKQ], wgor[RKQ];
#pragma unroll
    for (int r = 0; r < RKQ; ++r) {
        int k = k0 + r;
        wifr[r] = pack2(Whh[(0 * 128 + j) * 128 + k], Whh[(1 * 128 + j) * 128 + k]);
        wgor[r] = pack2(Whh[(2 * 128 + j) * 128 + k], Whh[(3 * 128 + j) * 128 + k]);
    }

    hbuf[th] = 0.f;                          // zero both ping-pong buffers
    float c = 0.f;                           // cell state (lanes kq<2 use it)

    const float* xgp = g_xg + (long)(b0 + row) * T_SEQ * 512;
    float p0 = 0.f, p1 = 0.f, p2 = 0.f, p3 = 0.f;
    if (kq < 2) {
        p0 = __ldg(xgp + j);       p1 = __ldg(xgp + 128 + j);
        p2 = __ldg(xgp + 256 + j); p3 = __ldg(xgp + 384 + j);
    }

    __syncthreads();

    for (int step = 0; step < T_SEQ; ++step) {
        const float* hc = hbuf + ((step & 1) << 8);
        float* hn = hbuf + (((step + 1) & 1) << 8);

        const float4* hA4 = (const float4*)(hc + k0);         // row 0, my k's
        const float4* hB4 = (const float4*)(hc + 128 + k0);   // row 1, my k's

        u64 aif0 = 0ull, ago0 = 0ull, aif1 = 0ull, ago1 = 0ull;

        // register k's: 5 float4 chunks (20 k)
#pragma unroll
        for (int q = 0; q < RKQ / 4; ++q) {
            float4 H0 = hA4[q], H1 = hB4[q];
#pragma unroll
            for (int cc = 0; cc < 4; ++cc) {
                int r = 4 * q + cc;
                float hx0 = (cc == 0) ? H0.x : (cc == 1) ? H0.y : (cc == 2) ? H0.z : H0.w;
                float hx1 = (cc == 0) ? H1.x : (cc == 1) ? H1.y : (cc == 2) ? H1.z : H1.w;
                u64 d0 = dup2(hx0), d1 = dup2(hx1);
                ffma2(aif0, wifr[r], d0); ffma2(ago0, wgor[r], d0);
                ffma2(aif1, wifr[r], d1); ffma2(ago1, wgor[r], d1);
            }
        }
        // smem k's: 3 float4 chunks (12 k)
#pragma unroll
        for (int q = 0; q < SKQ / 4; ++q) {
            float4 H0 = hA4[RKQ / 4 + q], H1 = hB4[RKQ / 4 + q];
            const float* pif = WIF + (kq * SKQ + 4 * q) * 256 + 2 * j;
            const float* pgo = WGO + (kq * SKQ + 4 * q) * 256 + 2 * j;
#pragma unroll
            for (int cc = 0; cc < 4; ++cc) {
                u64 wif = *(const u64*)(pif + cc * 256);
                u64 wgo = *(const u64*)(pgo + cc * 256);
                float hx0 = (cc == 0) ? H0.x : (cc == 1) ? H0.y : (cc == 2) ? H0.z : H0.w;
                float hx1 = (cc == 0) ? H1.x : (cc == 1) ? H1.y : (cc == 2) ? H1.z : H1.w;
                u64 d0 = dup2(hx0), d1 = dup2(hx1);
                ffma2(aif0, wif, d0); ffma2(ago0, wgo, d0);
                ffma2(aif1, wif, d1); ffma2(ago1, wgo, d1);
            }
        }

        // Warp-level reduction over kq for MY row only.
        // Round 1 (mask 8: kq0<->kq1, kq2<->kq3): partner's partial for my row.
        u64 aif = row ? aif1 : aif0;          // my row's own partial
        u64 ago = row ? ago1 : ago0;
        u64 oif = row ? aif0 : aif1;          // other row's partial -> partner
        u64 ogo = row ? ago0 : ago1;
        aif = add2(aif, __shfl_xor_sync(0xFFFFFFFFu, oif, 8));
        ago = add2(ago, __shfl_xor_sync(0xFFFFFFFFu, ogo, 8));
        // Round 2 (mask 16: kq0<->kq2, kq1<->kq3): same row, other k-half.
        aif = add2(aif, __shfl_xor_sync(0xFFFFFFFFu, aif, 16));
        ago = add2(ago, __shfl_xor_sync(0xFFFFFFFFu, ago, 16));

        if (kq < 2) {
            aif = add2(aif, pack2(p0, p1));
            ago = add2(ago, pack2(p2, p3));

            // prefetch next step's xg
            int ns = (step + 1 < T_SEQ) ? step + 1 : step;
            const float* qp = xgp + (long)ns * 512 + j;
            p0 = __ldg(qp); p1 = __ldg(qp + 128); p2 = __ldg(qp + 256); p3 = __ldg(qp + 384);

            float ai, af, ag, ao;
            unpack2(aif, ai, af); unpack2(ago, ag, ao);
            float iv = sigf(ai), fv = sigf(af), gv = tanhx(ag), ov = sigf(ao);
            c = fv * c + iv * gv;
            float nh = ov * tanhx(c);
            hn[(row << 7) + j] = nh;
        }
        __syncthreads();                      // single barrier per step
    }

    // Output projection (final h in buffer 0 since T_SEQ is even)
    if (th < 128) {
        int t = th;
        float acc0 = bo[t], acc1 = acc0;
        const float4* wo4 = (const float4*)(Wo + t * 128);
        const float4* h04 = (const float4*)hbuf;
        const float4* h14 = (const float4*)(hbuf + 128);
#pragma unroll
        for (int k4 = 0; k4 < 32; ++k4) {
            float4 wv = wo4[k4];
            float4 a = h04[k4];
            float4 b = h14[k4];
            acc0 += wv.x * a.x + wv.y * a.y + wv.z * a.z + wv.w * a.w;
            acc1 += wv.x * b.x + wv.y * b.y + wv.z * b.z + wv.w * b.w;
        }
        out[b0 * 128 + t] = acc0;
        out[(b0 + 1) * 128 + t] = acc1;
    }
}

// ---------------------------------------------------------------------------

extern "C" void kernel_launch(void* const* d_in, const int* in_sizes, int n_in,
                              void* d_out, int out_size)
{
    const float* x   = (const float*)d_in[0];
    const float* Wih = (const float*)d_in[1];
    const float* Whh = (const float*)d_in[2];
    const float* bih = (const float*)d_in[3];
    const float* bhh = (const float*)d_in[4];
    const float* Wo  = (const float*)d_in[5];
    const float* bo  = (const float*)d_in[6];
    float* out = (float*)d_out;

    // lstm_rec smem: WIF+WGO 2*(4*SKQ*256)*4 = 98304 B, hbuf 2048 B
    const int smB = 2 * (4 * SKQ * 256) * 4 + 2048;
    cudaFuncSetAttribute(xg_gemm, cudaFuncAttributeMaxDynamicSharedMemorySize, 98304);
    cudaFuncSetAttribute(lstm_rec, cudaFuncAttributeMaxDynamicSharedMemorySize, smB);

    xg_gemm<<<dim3(8192, 4), 256, 98304>>>(x, Wih, bih, bhh);
    lstm_rec<<<128, 512, smB>>>(Whh, Wo, bo, out);
}

// round 6
// speedup vs baseline: 1.3056x; 1.3056x over previous
#include <cuda_runtime.h>
#include <math.h>

#define T_SEQ 2048
#define BATCH 256
// Kernel B per k-quarter (32 k): RKQ in registers, SKQ in smem
#define RKQ 20
#define SKQ 12

typedef unsigned long long u64;

// xg scratch: [B][T][4H] fp32 = 1 GiB. __device__ global (no cudaMalloc allowed).
__device__ float g_xg[268435456];

// ---- f32x2 packed-math helpers (sm_103a FFMA2) --------------------------
__device__ __forceinline__ u64 pack2(float lo, float hi) {
    u64 r; asm("mov.b64 %0, {%1, %2};" : "=l"(r) : "f"(lo), "f"(hi)); return r;
}
__device__ __forceinline__ u64 dup2(float v) {
    u64 r; asm("mov.b64 %0, {%1, %1};" : "=l"(r) : "f"(v)); return r;
}
__device__ __forceinline__ void ffma2(u64& d, u64 a, u64 b) {
    asm("fma.rn.f32x2 %0, %1, %2, %0;" : "+l"(d) : "l"(a), "l"(b));
}
__device__ __forceinline__ u64 add2(u64 a, u64 b) {
    u64 r; asm("add.rn.f32x2 %0, %1, %2;" : "=l"(r) : "l"(a), "l"(b)); return r;
}
__device__ __forceinline__ void unpack2(u64 v, float& lo, float& hi) {
    asm("mov.b64 {%0, %1}, %2;" : "=f"(lo), "=f"(hi) : "l"(v));
}

// HW tanh (sm_75+): single instruction, abs err ~1e-4, saturates correctly.
__device__ __forceinline__ float tanhapx(float x) {
    float r; asm("tanh.approx.f32 %0, %1;" : "=f"(r) : "f"(x)); return r;
}
__device__ __forceinline__ float sigapx(float x) {
    return fmaf(0.5f, tanhapx(0.5f * x), 0.5f);   // sigmoid via tanh identity
}

// ---------------------------------------------------------------------------
// Kernel A: xg = x @ Wih^T + bih + bhh  (unchanged; ~95% of fp32x2 roofline)
// ---------------------------------------------------------------------------
__global__ void __launch_bounds__(256, 2)
xg_gemm(const float* __restrict__ x, const float* __restrict__ Wih,
        const float* __restrict__ bih, const float* __restrict__ bhh)
{
    extern __shared__ float sm[];
    float* As = sm;
    float* B0 = sm + 8192;
    float* B1 = B0 + 8192;

    const int tid = threadIdx.x;
    const int tx = tid & 31;
    const int ty = tid >> 5;
    const long row0 = (long)blockIdx.x * 64;
    const int g0 = blockIdx.y * 128;

    {
        const float4* x4 = (const float4*)x + row0 * 32;
        float4* As4 = (float4*)As;
#pragma unroll
        for (int i = 0; i < 8; ++i) As4[i * 256 + tid] = x4[i * 256 + tid];
    }
    {
        const float4* w4 = (const float4*)Wih + (long)g0 * 32;
#pragma unroll
        for (int i = 0; i < 16; ++i) {
            int idx = i * 256 + tid;
            int q  = idx >> 7;
            int gl = idx & 127;
            float4 w = w4[(long)gl * 32 + q];
            float* dst = (gl < 64 ? B0 : B1) + (gl & 63);
            int k = q * 4;
            dst[(k + 0) * 64] = w.x;
            dst[(k + 1) * 64] = w.y;
            dst[(k + 2) * 64] = w.z;
            dst[(k + 3) * 64] = w.w;
        }
    }
    __syncthreads();

    u64 acc0[8], acc1[8];
#pragma unroll
    for (int i = 0; i < 8; ++i) { acc0[i] = 0ull; acc1[i] = 0ull; }

    const float4* As4 = (const float4*)As;

#pragma unroll 2
    for (int k4 = 0; k4 < 32; ++k4) {
        float4 a[8];
#pragma unroll
        for (int i = 0; i < 8; ++i) a[i] = As4[(ty * 8 + i) * 32 + k4];
#pragma unroll
        for (int c = 0; c < 4; ++c) {
            int k = 4 * k4 + c;
            u64 b0 = *(const u64*)(B0 + k * 64 + 2 * tx);
            u64 b1 = *(const u64*)(B1 + k * 64 + 2 * tx);
#pragma unroll
            for (int i = 0; i < 8; ++i) {
                float av = (c == 0) ? a[i].x : (c == 1) ? a[i].y
                          : (c == 2) ? a[i].z : a[i].w;
                u64 ad = dup2(av);
                ffma2(acc0[i], ad, b0);
                ffma2(acc1[i], ad, b1);
            }
        }
    }

    int c00 = g0 + 2 * tx, c10 = g0 + 64 + 2 * tx;
    float2 bv0 = make_float2(bih[c00] + bhh[c00], bih[c00 + 1] + bhh[c00 + 1]);
    float2 bv1 = make_float2(bih[c10] + bhh[c10], bih[c10 + 1] + bhh[c10 + 1]);

#pragma unroll
    for (int i = 0; i < 8; ++i) {
        long r = row0 + ty * 8 + i;
        float lo, hi;
        unpack2(acc0[i], lo, hi);
        *(float2*)&g_xg[r * 512 + c00] = make_float2(lo + bv0.x, hi + bv0.y);
        unpack2(acc1[i], lo, hi);
        *(float2*)&g_xg[r * 512 + c10] = make_float2(lo + bv1.x, hi + bv1.y);
    }
}

// ---------------------------------------------------------------------------
// Kernel B: LSTM recurrence. 128 CTAs x 2 rows, 512 threads/CTA. (R4 topology)
// Thread (j, kq): j = th & 127, kq = th >> 7 owns 32 k's. RKQ=20 k in regs,
// SKQ=12 k in smem as INTERLEAVED float4 (wi,wf,wg,wo) -> one LDS.128 per k.
// Partials exchanged via smem; kq<2 finalize row=kq with HW tanh activations.
// ---------------------------------------------------------------------------
__global__ void __launch_bounds__(512, 1)
lstm_rec(const float* __restrict__ Whh, const float* __restrict__ Wo,
         const float* __restrict__ bo, float* __restrict__ out)
{
    extern __shared__ float sm[];
    float4* W4s = (float4*)sm;               // [48][128] (wi,wf,wg,wo) = 96 KB
    float* hbuf = sm + 48 * 128 * 4;         // [2][256] ping-pong (row*128+j)
    ulonglong2* part = (ulonglong2*)(hbuf + 512);  // [2][4][128] (aif,ago)

    const int th = threadIdx.x;
    const int j  = th & 127;
    const int kq = th >> 7;                  // k-quarter; also my row if kq<2
    const int b0 = blockIdx.x * 2;
    const int k0 = 32 * kq;

    // ---- smem weights: for each quarter q, k in [32q+RKQ, 32q+32)
    for (int e = th; e < 48 * 128; e += 512) {
        int jj = e & 127, ks = e >> 7;
        int q = ks / SKQ, kk = ks % SKQ;
        int k = 32 * q + RKQ + kk;
        W4s[ks * 128 + jj] = make_float4(
            Whh[(0 * 128 + jj) * 128 + k], Whh[(1 * 128 + jj) * 128 + k],
            Whh[(2 * 128 + jj) * 128 + k], Whh[(3 * 128 + jj) * 128 + k]);
    }
    // ---- register weights: k in [32kq, 32kq+RKQ)
    u64 wifr[RKQ], wgor[RKQ];
#pragma unroll
    for (int r = 0; r < RKQ; ++r) {
        int k = k0 + r;
        wifr[r] = pack2(Whh[(0 * 128 + j) * 128 + k], Whh[(1 * 128 + j) * 128 + k]);
        wgor[r] = pack2(Whh[(2 * 128 + j) * 128 + k], Whh[(3 * 128 + j) * 128 + k]);
    }

    hbuf[th] = 0.f;                          // zero both ping-pong buffers
    float c = 0.f;

    const float* xgp = g_xg + (long)(b0 + (kq & 1)) * T_SEQ * 512;
    float p0 = 0.f, p1 = 0.f, p2 = 0.f, p3 = 0.f;
    if (kq < 2) {
        p0 = __ldg(xgp + j);       p1 = __ldg(xgp + 128 + j);
        p2 = __ldg(xgp + 256 + j); p3 = __ldg(xgp + 384 + j);
    }

    __syncthreads();

    for (int step = 0; step < T_SEQ; ++step) {
        const float* hc = hbuf + ((step & 1) << 8);
        float* hn = hbuf + (((step + 1) & 1) << 8);

        const float4* hA4 = (const float4*)(hc + k0);         // row 0, my k's
        const float4* hB4 = (const float4*)(hc + 128 + k0);   // row 1, my k's

        u64 aif0 = 0ull, ago0 = 0ull, aif1 = 0ull, ago1 = 0ull;

        // register k's: 5 float4 chunks (20 k)
#pragma unroll
        for (int q = 0; q < RKQ / 4; ++q) {
            float4 H0 = hA4[q], H1 = hB4[q];
#pragma unroll
            for (int cc = 0; cc < 4; ++cc) {
                int r = 4 * q + cc;
                float hx0 = (cc == 0) ? H0.x : (cc == 1) ? H0.y : (cc == 2) ? H0.z : H0.w;
                float hx1 = (cc == 0) ? H1.x : (cc == 1) ? H1.y : (cc == 2) ? H1.z : H1.w;
                u64 d0 = dup2(hx0), d1 = dup2(hx1);
                ffma2(aif0, wifr[r], d0); ffma2(ago0, wgor[r], d0);
                ffma2(aif1, wifr[r], d1); ffma2(ago1, wgor[r], d1);
            }
        }
        // smem k's: 3 float4 h-chunks (12 k), weights via single LDS.128 per k
#pragma unroll
        for (int q = 0; q < SKQ / 4; ++q) {
            float4 H0 = hA4[RKQ / 4 + q], H1 = hB4[RKQ / 4 + q];
            const float4* wp = W4s + (kq * SKQ + 4 * q) * 128 + j;
#pragma unroll
            for (int cc = 0; cc < 4; ++cc) {
                float4 wv = wp[cc * 128];
                u64 wif = pack2(wv.x, wv.y);
                u64 wgo = pack2(wv.z, wv.w);
                float hx0 = (cc == 0) ? H0.x : (cc == 1) ? H0.y : (cc == 2) ? H0.z : H0.w;
                float hx1 = (cc == 0) ? H1.x : (cc == 1) ? H1.y : (cc == 2) ? H1.z : H1.w;
                u64 d0 = dup2(hx0), d1 = dup2(hx1);
                ffma2(aif0, wif, d0); ffma2(ago0, wgo, d0);
                ffma2(aif1, wif, d1); ffma2(ago1, wgo, d1);
            }
        }

        // exchange partials: P(row,kq,j) index = (row<<9) + (kq<<7) + j
        if (kq == 0) {
            part[(1 << 9) + (0 << 7) + j] = make_ulonglong2(aif1, ago1);
        } else if (kq == 1) {
            part[(0 << 9) + (1 << 7) + j] = make_ulonglong2(aif0, ago0);
        } else {
            part[(0 << 9) + (kq << 7) + j] = make_ulonglong2(aif0, ago0);
            part[(1 << 9) + (kq << 7) + j] = make_ulonglong2(aif1, ago1);
        }
        __syncthreads();

        if (kq < 2) {
            u64 aif = (kq == 0) ? aif0 : aif1;
            u64 ago = (kq == 0) ? ago0 : ago1;
#pragma unroll
            for (int qq = 1; qq < 4; ++qq) {
                int src = (kq + qq) & 3;
                ulonglong2 v = part[(kq << 9) + (src << 7) + j];
                aif = add2(aif, v.x);
                ago = add2(ago, v.y);
            }
            aif = add2(aif, pack2(p0, p1));
            ago = add2(ago, pack2(p2, p3));

            // prefetch next step's xg
            int ns = (step + 1 < T_SEQ) ? step + 1 : step;
            const float* qp = xgp + (long)ns * 512 + j;
            p0 = __ldg(qp); p1 = __ldg(qp + 128); p2 = __ldg(qp + 256); p3 = __ldg(qp + 384);

            float ai, af, ag, ao;
            unpack2(aif, ai, af); unpack2(ago, ag, ao);
            float iv = sigapx(ai), fv = sigapx(af), gv = tanhapx(ag), ov = sigapx(ao);
            c = fv * c + iv * gv;
            float nh = ov * tanhapx(c);
            hn[(kq << 7) + j] = nh;
        }
        __syncthreads();
    }

    // Output projection (final h in buffer 0 since T_SEQ is even)
    if (th < 128) {
        int t = th;
        float acc0 = bo[t], acc1 = acc0;
        const float4* wo4 = (const float4*)(Wo + t * 128);
        const float4* h04 = (const float4*)hbuf;
        const float4* h14 = (const float4*)(hbuf + 128);
#pragma unroll
        for (int k4 = 0; k4 < 32; ++k4) {
            float4 wv = wo4[k4];
            float4 a = h04[k4];
            float4 b = h14[k4];
            acc0 += wv.x * a.x + wv.y * a.y + wv.z * a.z + wv.w * a.w;
            acc1 += wv.x * b.x + wv.y * b.y + wv.z * b.z + wv.w * b.w;
        }
        out[b0 * 128 + t] = acc0;
        out[(b0 + 1) * 128 + t] = acc1;
    }
}

// ---------------------------------------------------------------------------

extern "C" void kernel_launch(void* const* d_in, const int* in_sizes, int n_in,
                              void* d_out, int out_size)
{
    const float* x   = (const float*)d_in[0];
    const float* Wih = (const float*)d_in[1];
    const float* Whh = (const float*)d_in[2];
    const float* bih = (const float*)d_in[3];
    const float* bhh = (const float*)d_in[4];
    const float* Wo  = (const float*)d_in[5];
    const float* bo  = (const float*)d_in[6];
    float* out = (float*)d_out;

    // lstm_rec smem: W4s 98304 B + hbuf 2048 B + part 16384 B = 116736 B
    const int smB = 98304 + 2048 + 16384;
    cudaFuncSetAttribute(xg_gemm, cudaFuncAttributeMaxDynamicSharedMemorySize, 98304);
    cudaFuncSetAttribute(lstm_rec, cudaFuncAttributeMaxDynamicSharedMemorySize, smB);

    xg_gemm<<<dim3(8192, 4), 256, 98304>>>(x, Wih, bih, bhh);
    lstm_rec<<<128, 512, smB>>>(Whh, Wo, bo, out);
}